// round 8
// baseline (speedup 1.0000x reference)
#include <cuda_runtime.h>
#include <cuda_fp16.h>
#include <cstdint>
#include <math.h>

#define B_  4
#define H_  12
#define S_  2048
#define D_  64
#define BH_ 48
#define QT  128
#define KC  128

// smem byte offsets (row stride 72 halves = 144 B, ldmatrix conflict-free)
#define OFF_QH 0
#define OFF_QL 18432
#define OFF_KH 36864
#define OFF_VH 55296
#define OFF_KM 73728                     // 128 floats (k-mask)
#define OFF_RL (OFF_KM + 512)            // 128 floats (1/l per q-row)
#define SMEM_BYTES (OFF_RL + 512)

__device__ __half g_e[(size_t)BH_ * S_ * S_];   // fp16 unnormalized e scratch (402 MB)

__device__ __forceinline__ uint32_t smem_u32(const void* p) {
    uint32_t a;
    asm("{ .reg .u64 t; cvta.to.shared.u64 t, %1; cvt.u32.u64 %0, t; }" : "=r"(a) : "l"(p));
    return a;
}

#define LDSM4(R0, R1, R2, R3, A) \
    asm volatile("ldmatrix.sync.aligned.m8n8.x4.shared.b16 {%0,%1,%2,%3}, [%4];" \
        : "=r"(R0), "=r"(R1), "=r"(R2), "=r"(R3) : "r"(A))
#define LDSM4T(R0, R1, R2, R3, A) \
    asm volatile("ldmatrix.sync.aligned.m8n8.x4.trans.shared.b16 {%0,%1,%2,%3}, [%4];" \
        : "=r"(R0), "=r"(R1), "=r"(R2), "=r"(R3) : "r"(A))

__device__ __forceinline__ void mma_f16(float* c, const uint32_t* a, uint32_t b0, uint32_t b1) {
    asm volatile("mma.sync.aligned.m16n8k16.row.col.f32.f16.f16.f32 "
        "{%0,%1,%2,%3}, {%4,%5,%6,%7}, {%8,%9}, {%0,%1,%2,%3};"
        : "+f"(c[0]), "+f"(c[1]), "+f"(c[2]), "+f"(c[3])
        : "r"(a[0]), "r"(a[1]), "r"(a[2]), "r"(a[3]), "r"(b0), "r"(b1));
}

__device__ __forceinline__ uint32_t packh2(__half a, __half b) {
    return (uint32_t)__half_as_ushort(a) | ((uint32_t)__half_as_ushort(b) << 16);
}

// fp16 hi/lo split of (x,y) into packed h16x2 words.
__device__ __forceinline__ void split2h(float x, float y, uint32_t& hi, uint32_t& lo) {
    __half hx = __float2half_rn(x), hy = __float2half_rn(y);
    float rx = x - __half2float(hx);
    float ry = y - __half2float(hy);
    hi = packh2(hx, hy);
    lo = packh2(__float2half_rn(rx), __float2half_rn(ry));
}

// 128x64 fp32 tile -> fp16 hi+lo smem (row stride 144 B). 256 threads.
__device__ __forceinline__ void load_tile_hilo(const float4* __restrict__ g,
                                               char* smem, uint32_t hoff, uint32_t loff, int tid)
{
#pragma unroll
    for (int i = 0; i < 8; ++i) {
        int idx = tid + 256 * i;
        int row = idx >> 4, c4 = idx & 15;
        float4 v = g[idx];
        uint32_t h0, l0, h1, l1;
        split2h(v.x, v.y, h0, l0);
        split2h(v.z, v.w, h1, l1);
        uint32_t off = row * 144 + c4 * 8;
        *(uint2*)(smem + hoff + off) = make_uint2(h0, h1);
        *(uint2*)(smem + loff + off) = make_uint2(l0, l1);
    }
}

// 128x64 fp32 tile -> fp16 (hi only) smem. 256 threads.
__device__ __forceinline__ void load_tile_hi(const float4* __restrict__ g,
                                             char* smem, uint32_t hoff, int tid)
{
#pragma unroll
    for (int i = 0; i < 8; ++i) {
        int idx = tid + 256 * i;
        int row = idx >> 4, c4 = idx & 15;
        float4 v = g[idx];
        uint32_t h0 = packh2(__float2half_rn(v.x), __float2half_rn(v.y));
        uint32_t h1 = packh2(__float2half_rn(v.z), __float2half_rn(v.w));
        *(uint2*)(smem + hoff + row * 144 + c4 * 8) = make_uint2(h0, h1);
    }
}

// ---------------------------------------------------------------------------
// Fused attention + normalization. Mainloop: QK^T ((qh+ql)*kh), exp/mask,
// fp16 e -> scratch, O += eh*vh. Tail: out = O/l, then re-read own e tile
// (L2-hot) and write p = e/l in fp32.
// ---------------------------------------------------------------------------
__global__ void __launch_bounds__(256, 2)
attn_kernel(const float* __restrict__ Q, const float* __restrict__ K,
            const float* __restrict__ V, const int* __restrict__ mask,
            float* __restrict__ out, float* __restrict__ p_out)
{
    extern __shared__ char sm[];
    const uint32_t smb = smem_u32(sm);
    float* kmf = (float*)(sm + OFF_KM);
    float* rls = (float*)(sm + OFF_RL);

    const int tid  = threadIdx.x;
    const int wid  = tid >> 5;
    const int lane = tid & 31;
    const int bh   = blockIdx.y;
    const int b    = bh / H_;
    const int q0   = blockIdx.x * QT;

    load_tile_hilo((const float4*)(Q + (size_t)(bh * S_ + q0) * D_), sm, OFF_QH, OFF_QL, tid);
    __syncthreads();

    // Hoist Q A-fragments (hi + lo) into registers
    uint32_t qh[4][4], ql[4][4];
    {
        uint32_t row = 16 * wid + (lane & 7) + ((lane >> 3) & 1) * 8;
        uint32_t base = smb + row * 144;
#pragma unroll
        for (int s = 0; s < 4; ++s) {
            uint32_t a = base + (s * 16 + (lane >> 4) * 8) * 2;
            LDSM4(qh[s][0], qh[s][1], qh[s][2], qh[s][3], a + OFF_QH);
            LDSM4(ql[s][0], ql[s][1], ql[s][2], ql[s][3], a + OFF_QL);
        }
    }

    const int rowa = q0 + 16 * wid + (lane >> 2);
    const int qm_a = mask[b * S_ + rowa];
    const int qm_b = mask[b * S_ + rowa + 8];
    const float qs_a = qm_a ? 0.125f : 0.0f;    // exp(0)=1 handles dead rows
    const float qs_b = qm_b ? 0.125f : 0.0f;

    float o[8][4];
#pragma unroll
    for (int i = 0; i < 8; ++i)
#pragma unroll
        for (int j = 0; j < 4; ++j) o[i][j] = 0.0f;
    float l_a = 0.0f, l_b = 0.0f;

    for (int kc = 0; kc < S_; kc += KC) {
        if (kc) __syncthreads();
        load_tile_hi((const float4*)(K + (size_t)(bh * S_ + kc) * D_), sm, OFF_KH, tid);
        load_tile_hi((const float4*)(V + (size_t)(bh * S_ + kc) * D_), sm, OFF_VH, tid);
        if (tid < KC) kmf[tid] = mask[b * S_ + kc + tid] ? 1.0f : 0.0f;
        __syncthreads();

#pragma unroll 1
        for (int s = 0; s < 8; ++s) {
            float c0[4] = {0.f, 0.f, 0.f, 0.f};
            float c1[4] = {0.f, 0.f, 0.f, 0.f};

            // ---- QK^T: (qh + ql) * kh ----
            {
                uint32_t brow = 16 * s + (lane & 7) + (lane >> 4) * 8;
                uint32_t bb = smb + brow * 144 + OFF_KH;
#pragma unroll
                for (int d = 0; d < 4; ++d) {
                    uint32_t a = bb + (d * 16 + ((lane >> 3) & 1) * 8) * 2;
                    uint32_t kh0, kh1, kh2, kh3;
                    LDSM4(kh0, kh1, kh2, kh3, a);
                    mma_f16(c0, qh[d], kh0, kh1);
                    mma_f16(c0, ql[d], kh0, kh1);
                    mma_f16(c1, qh[d], kh2, kh3);
                    mma_f16(c1, ql[d], kh2, kh3);
                }
            }

            // ---- exp + mask + row-sum partials ----
            const int col0 = 16 * s + 2 * (lane & 3);
            const float m00 = qm_a ? kmf[col0]     : 1.0f;
            const float m01 = qm_a ? kmf[col0 + 1] : 1.0f;
            const float m10 = qm_a ? kmf[col0 + 8] : 1.0f;
            const float m11 = qm_a ? kmf[col0 + 9] : 1.0f;
            const float n00 = qm_b ? kmf[col0]     : 1.0f;
            const float n01 = qm_b ? kmf[col0 + 1] : 1.0f;
            const float n10 = qm_b ? kmf[col0 + 8] : 1.0f;
            const float n11 = qm_b ? kmf[col0 + 9] : 1.0f;
            c0[0] = __expf(c0[0] * qs_a) * m00;
            c0[1] = __expf(c0[1] * qs_a) * m01;
            c0[2] = __expf(c0[2] * qs_b) * n00;
            c0[3] = __expf(c0[3] * qs_b) * n01;
            c1[0] = __expf(c1[0] * qs_a) * m10;
            c1[1] = __expf(c1[1] * qs_a) * m11;
            c1[2] = __expf(c1[2] * qs_b) * n10;
            c1[3] = __expf(c1[3] * qs_b) * n11;
            l_a += c0[0] + c0[1] + c1[0] + c1[1];
            l_b += c0[2] + c0[3] + c1[2] + c1[3];

            // ---- pack E fragments (fp16; C-layout == A-layout) ----
            uint32_t eh[4];
            eh[0] = packh2(__float2half_rn(c0[0]), __float2half_rn(c0[1]));
            eh[1] = packh2(__float2half_rn(c0[2]), __float2half_rn(c0[3]));
            eh[2] = packh2(__float2half_rn(c1[0]), __float2half_rn(c1[1]));
            eh[3] = packh2(__float2half_rn(c1[2]), __float2half_rn(c1[3]));

            // ---- store fp16 e to scratch (quad covers full 32B sectors) ----
            {
                __half* base0 = g_e + (size_t)(bh * S_ + rowa) * S_ + kc + col0;
                __half* base1 = g_e + (size_t)(bh * S_ + rowa + 8) * S_ + kc + col0;
                *(uint32_t*)(base0)     = eh[0];
                *(uint32_t*)(base0 + 8) = eh[2];
                *(uint32_t*)(base1)     = eh[1];
                *(uint32_t*)(base1 + 8) = eh[3];
            }

            // ---- O += eh * vh (single-term PV) ----
            {
                uint32_t vrow = 16 * s + (lane & 7) + ((lane >> 3) & 1) * 8;
                uint32_t vb = smb + vrow * 144 + OFF_VH;
#pragma unroll
                for (int d2 = 0; d2 < 4; ++d2) {
                    uint32_t a = vb + (d2 * 16 + (lane >> 4) * 8) * 2;
                    uint32_t vh0, vh1, vh2, vh3;
                    LDSM4T(vh0, vh1, vh2, vh3, a);
                    mma_f16(o[2 * d2], eh, vh0, vh1);
                    mma_f16(o[2 * d2 + 1], eh, vh2, vh3);
                }
            }
        }
    }

    // Quad reduction of row sums (lanes in a quad hold disjoint cols of same row)
    l_a += __shfl_xor_sync(0xFFFFFFFFu, l_a, 1);
    l_a += __shfl_xor_sync(0xFFFFFFFFu, l_a, 2);
    l_b += __shfl_xor_sync(0xFFFFFFFFu, l_b, 1);
    l_b += __shfl_xor_sync(0xFFFFFFFFu, l_b, 2);

    const float ra = 1.0f / l_a;
    const float rb = 1.0f / l_b;

    // out = O / l
    float* o0 = out + (size_t)(bh * S_ + rowa) * D_;
    float* o1 = out + (size_t)(bh * S_ + rowa + 8) * D_;
#pragma unroll
    for (int nt = 0; nt < 8; ++nt) {
        int col = nt * 8 + 2 * (lane & 3);
        *(float2*)(o0 + col) = make_float2(o[nt][0] * ra, o[nt][1] * ra);
        *(float2*)(o1 + col) = make_float2(o[nt][2] * rb, o[nt][3] * rb);
    }

    // Broadcast 1/l to the whole CTA via smem
    if ((lane & 3) == 0) {
        rls[rowa - q0]     = ra;
        rls[rowa - q0 + 8] = rb;
    }
    __syncthreads();   // also makes this CTA's global e stores visible to all its threads

    // ---- fused normalization: p = e / l (e tile is L2-hot) ----
    {
        const __half* esrc = g_e  + (size_t)(bh * S_ + q0) * S_;
        float*        pdst = p_out + (size_t)(bh * S_ + q0) * S_;
#pragma unroll 2
        for (int r = 0; r < QT; ++r) {
            const float rl = rls[r];
            uint4 ew = __ldcs((const uint4*)(esrc + (size_t)r * S_) + tid);
            const __half2* h2 = (const __half2*)&ew;
            float2 a0 = __half22float2(h2[0]);
            float2 a1 = __half22float2(h2[1]);
            float2 a2 = __half22float2(h2[2]);
            float2 a3 = __half22float2(h2[3]);
            float4 v0 = make_float4(a0.x * rl, a0.y * rl, a1.x * rl, a1.y * rl);
            float4 v1 = make_float4(a2.x * rl, a2.y * rl, a3.x * rl, a3.y * rl);
            float4* dst = (float4*)(pdst + (size_t)r * S_) + tid * 2;
            __stcs(dst,     v0);
            __stcs(dst + 1, v1);
        }
    }
}

// ---------------------------------------------------------------------------
extern "C" void kernel_launch(void* const* d_in, const int* in_sizes, int n_in,
                              void* d_out, int out_size)
{
    (void)in_sizes; (void)n_in; (void)out_size;
    const float* Q    = (const float*)d_in[0];
    const float* K    = (const float*)d_in[1];
    const float* V    = (const float*)d_in[2];
    const int*   mask = (const int*)d_in[3];

    float* out = (float*)d_out;                       // [B,H,S,D]
    float* p   = out + (size_t)B_ * H_ * S_ * D_;     // [B,H,S,S]

    cudaFuncSetAttribute(attn_kernel, cudaFuncAttributeMaxDynamicSharedMemorySize, SMEM_BYTES);

    dim3 grid(S_ / QT, BH_);
    attn_kernel<<<grid, 256, SMEM_BYTES>>>(Q, K, V, mask, out, p);
}

// round 10
// speedup vs baseline: 1.2164x; 1.2164x over previous
#include <cuda_runtime.h>
#include <cuda_fp16.h>
#include <cstdint>
#include <math.h>

#define B_  4
#define H_  12
#define S_  2048
#define D_  64
#define BH_ 48
#define QT  128
#define KC  128

// smem byte offsets (row stride 72 halves = 144 B, ldmatrix conflict-free)
#define OFF_QH 0
#define OFF_KH 18432
#define OFF_VH 36864
#define OFF_KM 55296
#define SMEM_BYTES (OFF_KM + 512)

__device__ float  g_l[BH_ * S_];
__device__ __half g_e[(size_t)BH_ * S_ * S_];   // fp16 unnormalized e scratch (402 MB)

__device__ __forceinline__ uint32_t smem_u32(const void* p) {
    uint32_t a;
    asm("{ .reg .u64 t; cvta.to.shared.u64 t, %1; cvt.u32.u64 %0, t; }" : "=r"(a) : "l"(p));
    return a;
}

#define LDSM4(R0, R1, R2, R3, A) \
    asm volatile("ldmatrix.sync.aligned.m8n8.x4.shared.b16 {%0,%1,%2,%3}, [%4];" \
        : "=r"(R0), "=r"(R1), "=r"(R2), "=r"(R3) : "r"(A))
#define LDSM4T(R0, R1, R2, R3, A) \
    asm volatile("ldmatrix.sync.aligned.m8n8.x4.trans.shared.b16 {%0,%1,%2,%3}, [%4];" \
        : "=r"(R0), "=r"(R1), "=r"(R2), "=r"(R3) : "r"(A))

__device__ __forceinline__ void mma_f16(float* c, const uint32_t* a, uint32_t b0, uint32_t b1) {
    asm volatile("mma.sync.aligned.m16n8k16.row.col.f32.f16.f16.f32 "
        "{%0,%1,%2,%3}, {%4,%5,%6,%7}, {%8,%9}, {%0,%1,%2,%3};"
        : "+f"(c[0]), "+f"(c[1]), "+f"(c[2]), "+f"(c[3])
        : "r"(a[0]), "r"(a[1]), "r"(a[2]), "r"(a[3]), "r"(b0), "r"(b1));
}

__device__ __forceinline__ uint32_t packh2(__half a, __half b) {
    return (uint32_t)__half_as_ushort(a) | ((uint32_t)__half_as_ushort(b) << 16);
}

// 128x64 fp32 tile -> fp16 smem (row stride 144 B). 256 threads.
__device__ __forceinline__ void load_tile_hi(const float4* __restrict__ g,
                                             char* smem, uint32_t hoff, int tid)
{
#pragma unroll
    for (int i = 0; i < 8; ++i) {
        int idx = tid + 256 * i;
        int row = idx >> 4, c4 = idx & 15;
        float4 v = g[idx];
        uint32_t h0 = packh2(__float2half_rn(v.x), __float2half_rn(v.y));
        uint32_t h1 = packh2(__float2half_rn(v.z), __float2half_rn(v.w));
        *(uint2*)(smem + hoff + row * 144 + c4 * 8) = make_uint2(h0, h1);
    }
}

// ---------------------------------------------------------------------------
// Fused attention: QK^T (single fp16 term qh*kh, 4-deep chains) -> exp/mask ->
// fp16 e to scratch, O += eh*vh. mma.sync m16n8k16, fp32 accumulate.
// ---------------------------------------------------------------------------
__global__ void __launch_bounds__(256, 2)
attn_kernel(const float* __restrict__ Q, const float* __restrict__ K,
            const float* __restrict__ V, const int* __restrict__ mask,
            float* __restrict__ out)
{
    extern __shared__ char sm[];
    const uint32_t smb = smem_u32(sm);
    float* kmf = (float*)(sm + OFF_KM);

    const int tid  = threadIdx.x;
    const int wid  = tid >> 5;
    const int lane = tid & 31;
    const int bh   = blockIdx.y;
    const int b    = bh / H_;
    const int q0   = blockIdx.x * QT;

    load_tile_hi((const float4*)(Q + (size_t)(bh * S_ + q0) * D_), sm, OFF_QH, tid);
    __syncthreads();

    // Hoist Q A-fragments into registers (persistent)
    uint32_t qh[4][4];
    {
        uint32_t row = 16 * wid + (lane & 7) + ((lane >> 3) & 1) * 8;
        uint32_t base = smb + row * 144;
#pragma unroll
        for (int s = 0; s < 4; ++s) {
            uint32_t a = base + (s * 16 + (lane >> 4) * 8) * 2;
            LDSM4(qh[s][0], qh[s][1], qh[s][2], qh[s][3], a + OFF_QH);
        }
    }

    const int rowa = q0 + 16 * wid + (lane >> 2);
    const int qm_a = mask[b * S_ + rowa];
    const int qm_b = mask[b * S_ + rowa + 8];
    const float qs_a = qm_a ? 0.125f : 0.0f;    // exp(0)=1 handles dead rows
    const float qs_b = qm_b ? 0.125f : 0.0f;

    float o[8][4];
#pragma unroll
    for (int i = 0; i < 8; ++i)
#pragma unroll
        for (int j = 0; j < 4; ++j) o[i][j] = 0.0f;
    float l_a = 0.0f, l_b = 0.0f;

    for (int kc = 0; kc < S_; kc += KC) {
        if (kc) __syncthreads();
        load_tile_hi((const float4*)(K + (size_t)(bh * S_ + kc) * D_), sm, OFF_KH, tid);
        load_tile_hi((const float4*)(V + (size_t)(bh * S_ + kc) * D_), sm, OFF_VH, tid);
        if (tid < KC) kmf[tid] = mask[b * S_ + kc + tid] ? 1.0f : 0.0f;
        __syncthreads();

#pragma unroll 1
        for (int s = 0; s < 8; ++s) {
            float c0[4] = {0.f, 0.f, 0.f, 0.f};
            float c1[4] = {0.f, 0.f, 0.f, 0.f};

            // ---- QK^T: qh * kh (two independent 4-deep chains) ----
            {
                uint32_t brow = 16 * s + (lane & 7) + (lane >> 4) * 8;
                uint32_t bb = smb + brow * 144 + OFF_KH;
#pragma unroll
                for (int d = 0; d < 4; ++d) {
                    uint32_t a = bb + (d * 16 + ((lane >> 3) & 1) * 8) * 2;
                    uint32_t kh0, kh1, kh2, kh3;
                    LDSM4(kh0, kh1, kh2, kh3, a);
                    mma_f16(c0, qh[d], kh0, kh1);
                    mma_f16(c1, qh[d], kh2, kh3);
                }
            }

            // ---- exp + mask + row-sum partials ----
            const int col0 = 16 * s + 2 * (lane & 3);
            const float m00 = qm_a ? kmf[col0]     : 1.0f;
            const float m01 = qm_a ? kmf[col0 + 1] : 1.0f;
            const float m10 = qm_a ? kmf[col0 + 8] : 1.0f;
            const float m11 = qm_a ? kmf[col0 + 9] : 1.0f;
            const float n00 = qm_b ? kmf[col0]     : 1.0f;
            const float n01 = qm_b ? kmf[col0 + 1] : 1.0f;
            const float n10 = qm_b ? kmf[col0 + 8] : 1.0f;
            const float n11 = qm_b ? kmf[col0 + 9] : 1.0f;
            c0[0] = __expf(c0[0] * qs_a) * m00;
            c0[1] = __expf(c0[1] * qs_a) * m01;
            c0[2] = __expf(c0[2] * qs_b) * n00;
            c0[3] = __expf(c0[3] * qs_b) * n01;
            c1[0] = __expf(c1[0] * qs_a) * m10;
            c1[1] = __expf(c1[1] * qs_a) * m11;
            c1[2] = __expf(c1[2] * qs_b) * n10;
            c1[3] = __expf(c1[3] * qs_b) * n11;
            l_a += c0[0] + c0[1] + c1[0] + c1[1];
            l_b += c0[2] + c0[3] + c1[2] + c1[3];

            // ---- pack E fragments (fp16; C-layout == A-layout) ----
            uint32_t eh[4];
            eh[0] = packh2(__float2half_rn(c0[0]), __float2half_rn(c0[1]));
            eh[1] = packh2(__float2half_rn(c0[2]), __float2half_rn(c0[3]));
            eh[2] = packh2(__float2half_rn(c1[0]), __float2half_rn(c1[1]));
            eh[3] = packh2(__float2half_rn(c1[2]), __float2half_rn(c1[3]));

            // ---- store fp16 e to scratch (quad covers full 32B sectors) ----
            {
                __half* base0 = g_e + (size_t)(bh * S_ + rowa) * S_ + kc + col0;
                __half* base1 = g_e + (size_t)(bh * S_ + rowa + 8) * S_ + kc + col0;
                *(uint32_t*)(base0)     = eh[0];
                *(uint32_t*)(base0 + 8) = eh[2];
                *(uint32_t*)(base1)     = eh[1];
                *(uint32_t*)(base1 + 8) = eh[3];
            }

            // ---- O += eh * vh (single-term PV; 8 independent targets) ----
            {
                uint32_t vrow = 16 * s + (lane & 7) + ((lane >> 3) & 1) * 8;
                uint32_t vb = smb + vrow * 144 + OFF_VH;
#pragma unroll
                for (int d2 = 0; d2 < 4; ++d2) {
                    uint32_t a = vb + (d2 * 16 + (lane >> 4) * 8) * 2;
                    uint32_t vh0, vh1, vh2, vh3;
                    LDSM4T(vh0, vh1, vh2, vh3, a);
                    mma_f16(o[2 * d2], eh, vh0, vh1);
                    mma_f16(o[2 * d2 + 1], eh, vh2, vh3);
                }
            }
        }
    }

    // Quad reduction of row sums (lanes in a quad hold disjoint cols of same row)
    l_a += __shfl_xor_sync(0xFFFFFFFFu, l_a, 1);
    l_a += __shfl_xor_sync(0xFFFFFFFFu, l_a, 2);
    l_b += __shfl_xor_sync(0xFFFFFFFFu, l_b, 1);
    l_b += __shfl_xor_sync(0xFFFFFFFFu, l_b, 2);

    const float ra = 1.0f / l_a;
    const float rb = 1.0f / l_b;
    float* o0 = out + (size_t)(bh * S_ + rowa) * D_;
    float* o1 = out + (size_t)(bh * S_ + rowa + 8) * D_;
#pragma unroll
    for (int nt = 0; nt < 8; ++nt) {
        int col = nt * 8 + 2 * (lane & 3);
        *(float2*)(o0 + col) = make_float2(o[nt][0] * ra, o[nt][1] * ra);
        *(float2*)(o1 + col) = make_float2(o[nt][2] * rb, o[nt][3] * rb);
    }
    if ((lane & 3) == 0) {
        g_l[bh * S_ + rowa] = l_a;
        g_l[bh * S_ + rowa + 8] = l_b;
    }
}

// ---------------------------------------------------------------------------
// Normalize: p(fp32) = e(fp16) / l. One block per q-row; thread reads 8 halves
// (uint4), writes 2 float4. Streaming hints (no reuse).
// ---------------------------------------------------------------------------
__global__ void __launch_bounds__(256)
norm_kernel(float4* __restrict__ p)
{
    const int row = blockIdx.x;
    const float rl = 1.0f / g_l[row];
    const uint4* src = (const uint4*)(g_e + (size_t)row * S_) + threadIdx.x;
    uint4 ew = __ldcs(src);
    const __half2* h2 = (const __half2*)&ew;
    float2 a0 = __half22float2(h2[0]);
    float2 a1 = __half22float2(h2[1]);
    float2 a2 = __half22float2(h2[2]);
    float2 a3 = __half22float2(h2[3]);
    float4 v0 = make_float4(a0.x * rl, a0.y * rl, a1.x * rl, a1.y * rl);
    float4 v1 = make_float4(a2.x * rl, a2.y * rl, a3.x * rl, a3.y * rl);
    float4* dst = p + (size_t)row * (S_ / 4) + threadIdx.x * 2;
    __stcs(dst,     v0);
    __stcs(dst + 1, v1);
}

// ---------------------------------------------------------------------------
extern "C" void kernel_launch(void* const* d_in, const int* in_sizes, int n_in,
                              void* d_out, int out_size)
{
    (void)in_sizes; (void)n_in; (void)out_size;
    const float* Q    = (const float*)d_in[0];
    const float* K    = (const float*)d_in[1];
    const float* V    = (const float*)d_in[2];
    const int*   mask = (const int*)d_in[3];

    float* out = (float*)d_out;                       // [B,H,S,D]
    float* p   = out + (size_t)B_ * H_ * S_ * D_;     // [B,H,S,S]

    cudaFuncSetAttribute(attn_kernel, cudaFuncAttributeMaxDynamicSharedMemorySize, SMEM_BYTES);

    dim3 grid(S_ / QT, BH_);
    attn_kernel<<<grid, 256, SMEM_BYTES>>>(Q, K, V, mask, out);

    norm_kernel<<<BH_ * S_, 256>>>((float4*)p);
}